// round 5
// baseline (speedup 1.0000x reference)
#include <cuda_runtime.h>
#include <math.h>

#define AA 48
#define NDP 1128        // nondiag pairs
#define STEPS 23
#define ROW 1176        // AA + NDP
#define BPB 4           // batches per block
#define THREADS 320
#define Q4 (ROW / 4)    // 294 output columns per thread-slice
#define LUTW 9          // per-column LUT width (cls = u'i + u'j in 0..8)

__device__ float g_lut[ROW * LUTW];  // unified per-output-column 9-entry LUT
__device__ int   g_pair[NDP];        // iy | (ix<<8)

__global__ void setup_kernel(const float* __restrict__ ed,
                             const float* __restrict__ en) {
    int k = blockIdx.x * blockDim.x + threadIdx.x;
    if (k < AA) {
        // diag column k: u'i == u'j -> sums {0,2,8} -> {0, sig, 1}
        float s = 1.f / (1.f + expf(-ed[k]));
        float* L = &g_lut[k * LUTW];
        #pragma unroll
        for (int c = 0; c < LUTW; ++c) L[c] = 0.f;
        L[2] = s;
        L[8] = 1.f;
    }
    if (k < NDP) {
        float f12 = 1.f / (1.f + expf(-en[k * 4 + 0]));
        float f9  = 1.f / (1.f + expf(-en[k * 4 + 1])) * f12;
        float f8  = 1.f / (1.f + expf(-en[k * 4 + 2])) * f9;
        float f6  = 1.f / (1.f + expf(-en[k * 4 + 3])) * f8;
        // u' in {0,1,4}: sum cls -> product: 0->4:0  1->6:f6  2->9:f9
        // 4->8:f8  5->12:f12  8->16:1
        float* L = &g_lut[(AA + k) * LUTW];
        L[0] = 0.f; L[1] = f6;  L[2] = f9; L[3] = 0.f;
        L[4] = f8;  L[5] = f12; L[6] = 0.f; L[7] = 0.f;
        L[8] = 1.f;
        int rem = k, iy = 0;
        while (rem >= AA - 1 - iy) { rem -= AA - 1 - iy; ++iy; }
        int ix = iy + 1 + rem;
        g_pair[k] = iy | (ix << 8);
    }
}

__global__ __launch_bounds__(THREADS, 4)
void main_kernel(const int* __restrict__ x, float* __restrict__ out) {
    __shared__ float         s_lut[ROW * LUTW];        // 42336 B
    __shared__ unsigned char s_u[BPB][STEPS][AA];      //  4416 B

    const int tid = threadIdx.x;
    const int b0  = blockIdx.x * BPB;

    // ---- LUT copy (float4) ----
    {
        const float4* src = reinterpret_cast<const float4*>(g_lut);
        float4*       dst = reinterpret_cast<float4*>(s_lut);
        for (int i = tid; i < (ROW * LUTW) / 4; i += THREADS)
            dst[i] = __ldg(src + i);
    }

    // ---- phase 1: integer recurrence, one thread per (q, column) ----
    if (tid < BPB * AA) {
        int q = tid / AA;
        int j = tid - q * AA;
        const int* xb = x + (long)(b0 + q) * (25 * AA) + j;
        unsigned int v = 0;
        #pragma unroll
        for (int r = 0; r < 25; ++r)
            v |= ((unsigned int)__ldg(xb + r * AA)) << r;

        int st = -1, dt = 1;
        #pragma unroll
        for (int r = 0; r < STEPS; ++r) {
            int a  = (v >> r)       & 1;
            int bb = (v >> (r + 1)) & 1;
            int c  = (v >> (r + 2)) & 1;
            int de = a ^ c;
            int me = bb * (1 - (a + c)) + a * c;
            dt = dt * (1 - 2 * me);
            st = st + dt * de;
            st = st < -1 ? -1 : (st > 1 ? 1 : st);
            int ome = 1 - me;
            dt = dt * (1 - st * st * ome) - st * ome;
            int u = st + 1;                 // 0,1,2
            u = u + (u & 2);                // remap 2 -> 4
            s_u[q][r][j] = (unsigned char)u;
        }
    }
    __syncthreads();

    // ---- phase 2: one thread per column t; columns t, t+294, t+588, t+882 ----
    const int t = tid;
    if (t >= Q4) return;   // 294 active threads

    int off_i[4], off_j[4], lutb[4];
    #pragma unroll
    for (int e = 0; e < 4; ++e) {
        int k = t + Q4 * e;
        int ii, jj;
        if (k < AA) { ii = jj = k; }
        else {
            int p = __ldg(&g_pair[k - AA]);
            ii = p & 255; jj = p >> 8;
        }
        off_i[e] = ii;
        off_j[e] = jj;
        lutb[e]  = k * LUTW;
    }

    #pragma unroll
    for (int q = 0; q < BPB; ++q) {
        const unsigned char* uq = &s_u[q][0][0];
        float* ob = out + ((long)(b0 + q) * STEPS) * ROW + t;

        int r = 0;
        // ---- unrolled-by-2 rows: batch all 16 byte loads, then 8 LUT loads ----
        for (; r + 1 < STEPS; r += 2) {
            const unsigned char* u0 = uq + r * AA;
            const unsigned char* u1 = u0 + AA;
            int bi[8], bj[8];
            #pragma unroll
            for (int e = 0; e < 4; ++e) {
                bi[e]     = (int)u0[off_i[e]];
                bj[e]     = (int)u0[off_j[e]];
                bi[e + 4] = (int)u1[off_i[e]];
                bj[e + 4] = (int)u1[off_j[e]];
            }
            float vv[8];
            #pragma unroll
            for (int e = 0; e < 8; ++e)
                vv[e] = s_lut[lutb[e & 3] + bi[e] + bj[e]];

            float* o0 = ob + (long)r * ROW;
            float* o1 = o0 + ROW;
            #pragma unroll
            for (int e = 0; e < 4; ++e) {
                __stcs(o0 + Q4 * e, vv[e]);
                __stcs(o1 + Q4 * e, vv[e + 4]);
            }
        }
        // ---- tail row (STEPS is odd) ----
        {
            const unsigned char* u0 = uq + r * AA;
            float* o0 = ob + (long)r * ROW;
            int bi[4], bj[4];
            #pragma unroll
            for (int e = 0; e < 4; ++e) {
                bi[e] = (int)u0[off_i[e]];
                bj[e] = (int)u0[off_j[e]];
            }
            #pragma unroll
            for (int e = 0; e < 4; ++e)
                __stcs(o0 + Q4 * e, s_lut[lutb[e] + bi[e] + bj[e]]);
        }
    }
}

extern "C" void kernel_launch(void* const* d_in, const int* in_sizes, int n_in,
                              void* d_out, int out_size) {
    const int*   x  = (const int*)d_in[0];     // (4096, 25, 48) int32
    const float* ed = (const float*)d_in[1];   // (1, 48) f32
    const float* en = (const float*)d_in[2];   // (1, 1128, 4) f32
    float* out = (float*)d_out;                // (4096, 23, 1176) f32

    setup_kernel<<<(NDP + 255) / 256, 256>>>(ed, en);
    int nb = in_sizes[0] / (25 * AA);          // 4096 batches
    main_kernel<<<nb / BPB, THREADS>>>(x, out);
}

// round 6
// speedup vs baseline: 1.0989x; 1.0989x over previous
#include <cuda_runtime.h>
#include <math.h>

#define AA 48
#define NDP 1128        // nondiag pairs
#define STEPS 23
#define ROW 1176        // AA + NDP
#define BPB 2           // batches per block
#define THREADS 320
#define Q4 (ROW / 4)    // 294 output columns per thread-slice
#define LUTW 7          // per-column LUT width (cls = u'i + u'j in 0..6)

__device__ float g_lut[ROW * LUTW];  // unified per-output-column 7-entry LUT
__device__ int   g_pair[NDP];        // iy | (ix<<8)

__global__ void setup_kernel(const float* __restrict__ ed,
                             const float* __restrict__ en) {
    int k = blockIdx.x * blockDim.x + threadIdx.x;
    if (k < AA) {
        // diag column k: u'i == u'j -> sums {0,2,6} -> {0, sig, 1}
        float s = 1.f / (1.f + expf(-ed[k]));
        float* L = &g_lut[k * LUTW];
        #pragma unroll
        for (int c = 0; c < LUTW; ++c) L[c] = 0.f;
        L[2] = s;
        L[6] = 1.f;
    }
    if (k < NDP) {
        float f12 = 1.f / (1.f + expf(-en[k * 4 + 0]));
        float f9  = 1.f / (1.f + expf(-en[k * 4 + 1])) * f12;
        float f8  = 1.f / (1.f + expf(-en[k * 4 + 2])) * f9;
        float f6  = 1.f / (1.f + expf(-en[k * 4 + 3])) * f8;
        // u' in {0,1,3}, xx = u'+2 mapped {2,3,4}:
        // cls 0:(2*2=4)->0   1:(2*3=6)->f6   2:(3*3=9)->f9
        // cls 3:(2*4=8)->f8  4:(3*4=12)->f12 6:(4*4=16)->1
        float* L = &g_lut[(AA + k) * LUTW];
        L[0] = 0.f; L[1] = f6;  L[2] = f9;
        L[3] = f8;  L[4] = f12; L[5] = 0.f;
        L[6] = 1.f;
        int rem = k, iy = 0;
        while (rem >= AA - 1 - iy) { rem -= AA - 1 - iy; ++iy; }
        int ix = iy + 1 + rem;
        g_pair[k] = iy | (ix << 8);
    }
}

__global__ __launch_bounds__(THREADS)
void main_kernel(const int* __restrict__ x, float* __restrict__ out) {
    __shared__ float         s_lut[ROW * LUTW];        // 32928 B
    __shared__ unsigned char s_u[BPB][STEPS][AA];      //  2208 B

    const int tid = threadIdx.x;
    const int b0  = blockIdx.x * BPB;

    // ---- LUT copy (float4, 2058 vectors) ----
    {
        const float4* src = reinterpret_cast<const float4*>(g_lut);
        float4*       dst = reinterpret_cast<float4*>(s_lut);
        for (int i = tid; i < (ROW * LUTW) / 4; i += THREADS)
            dst[i] = __ldg(src + i);
    }

    // ---- phase 1: integer recurrence, one thread per (q, column) ----
    if (tid < BPB * AA) {
        int q = tid / AA;
        int j = tid - q * AA;
        const int* xb = x + (long)(b0 + q) * (25 * AA) + j;
        unsigned int v = 0;
        #pragma unroll
        for (int r = 0; r < 25; ++r)
            v |= ((unsigned int)__ldg(xb + r * AA)) << r;

        int st = -1, dt = 1;
        #pragma unroll
        for (int r = 0; r < STEPS; ++r) {
            int a  = (v >> r)       & 1;
            int bb = (v >> (r + 1)) & 1;
            int c  = (v >> (r + 2)) & 1;
            int de = a ^ c;
            int me = bb * (1 - (a + c)) + a * c;
            dt = dt * (1 - 2 * me);
            st = st + dt * de;
            st = st < -1 ? -1 : (st > 1 ? 1 : st);
            int ome = 1 - me;
            dt = dt * (1 - st * st * ome) - st * ome;
            int u = st + 1;                 // 0,1,2
            u = u + (u >> 1);               // remap 2 -> 3
            s_u[q][r][j] = (unsigned char)u;
        }
    }
    __syncthreads();

    // ---- phase 2: one thread per column t; columns t, t+294, t+588, t+882 ----
    const int t = tid;
    if (t >= Q4) return;   // 294 active threads

    int off_i[4], off_j[4], lutb[4];
    #pragma unroll
    for (int e = 0; e < 4; ++e) {
        int k = t + Q4 * e;
        int ii, jj;
        if (k < AA) { ii = jj = k; }
        else {
            int p = __ldg(&g_pair[k - AA]);
            ii = p & 255; jj = p >> 8;
        }
        off_i[e] = ii;
        off_j[e] = jj;
        lutb[e]  = k * LUTW;
    }

    #pragma unroll
    for (int q = 0; q < BPB; ++q) {
        const unsigned char* uq = &s_u[q][0][0];
        float* ob = out + ((long)(b0 + q) * STEPS) * ROW + t;
        for (int r = 0; r < STEPS; ++r) {
            const unsigned char* u = uq + r * AA;
            float* orow = ob + (long)r * ROW;
            #pragma unroll
            for (int e = 0; e < 4; ++e) {
                int cls = (int)u[off_i[e]] + (int)u[off_j[e]];
                __stcs(orow + Q4 * e, s_lut[lutb[e] + cls]);
            }
        }
    }
}

extern "C" void kernel_launch(void* const* d_in, const int* in_sizes, int n_in,
                              void* d_out, int out_size) {
    const int*   x  = (const int*)d_in[0];     // (4096, 25, 48) int32
    const float* ed = (const float*)d_in[1];   // (1, 48) f32
    const float* en = (const float*)d_in[2];   // (1, 1128, 4) f32
    float* out = (float*)d_out;                // (4096, 23, 1176) f32

    setup_kernel<<<(NDP + 255) / 256, 256>>>(ed, en);
    int nb = in_sizes[0] / (25 * AA);          // 4096 batches
    main_kernel<<<nb / BPB, THREADS>>>(x, out);
}

// round 7
// speedup vs baseline: 1.3528x; 1.2311x over previous
#include <cuda_runtime.h>
#include <math.h>

#define AA 48
#define NDP 1128        // nondiag pairs
#define STEPS 23
#define ROW 1176        // AA + NDP
#define BPB 2           // batches per block
#define THREADS 320
#define Q4 (ROW / 4)    // 294 column-groups (one per thread)
#define LUTW 7          // cls = u'i + u'j in 0..6, u' in {0,1,3}
#define USTRIDE 52      // padded state row: 48 data + 4 zero bytes

// interleaved LUT: entry (k, cls) at (k&3)*Q4*LUTW + (k>>2)*LUTW + cls
__device__ float g_lut[ROW * LUTW];
__device__ int   g_pair[NDP];        // iy | (ix<<8)

__global__ void setup_kernel(const float* __restrict__ ed,
                             const float* __restrict__ en) {
    int k = blockIdx.x * blockDim.x + threadIdx.x;
    if (k < AA) {
        // diag column k: ii -> zero pad, so cls = u'j in {0,1,3}
        float s = 1.f / (1.f + expf(-ed[k]));
        float* L = &g_lut[(k & 3) * (Q4 * LUTW) + (k >> 2) * LUTW];
        #pragma unroll
        for (int c = 0; c < LUTW; ++c) L[c] = 0.f;
        L[1] = s;     // u'j == 1  (st == 0)
        L[3] = 1.f;   // u'j == 3  (st == 1)
        // L[0] = 0   (st == -1)
    }
    if (k < NDP) {
        float f12 = 1.f / (1.f + expf(-en[k * 4 + 0]));
        float f9  = 1.f / (1.f + expf(-en[k * 4 + 1])) * f12;
        float f8  = 1.f / (1.f + expf(-en[k * 4 + 2])) * f9;
        float f6  = 1.f / (1.f + expf(-en[k * 4 + 3])) * f8;
        // u' in {0,1,3}: cls -> product: 0->4:0  1->6:f6  2->9:f9
        // 3->8:f8  4->12:f12  6->16:1
        int kk = AA + k;
        float* L = &g_lut[(kk & 3) * (Q4 * LUTW) + (kk >> 2) * LUTW];
        L[0] = 0.f; L[1] = f6;  L[2] = f9;
        L[3] = f8;  L[4] = f12; L[5] = 0.f;
        L[6] = 1.f;
        int rem = k, iy = 0;
        while (rem >= AA - 1 - iy) { rem -= AA - 1 - iy; ++iy; }
        int ix = iy + 1 + rem;
        g_pair[k] = iy | (ix << 8);
    }
}

__global__ __launch_bounds__(THREADS)
void main_kernel(const int* __restrict__ x, float* __restrict__ out) {
    __shared__ float         s_lut[ROW * LUTW];            // 32928 B
    __shared__ unsigned char s_u[BPB][STEPS * USTRIDE];    //  2392 B

    const int tid = threadIdx.x;
    const int b0  = blockIdx.x * BPB;

    // ---- LUT copy (float4, 2058 vectors) ----
    {
        const float4* src = reinterpret_cast<const float4*>(g_lut);
        float4*       dst = reinterpret_cast<float4*>(s_lut);
        for (int i = tid; i < (ROW * LUTW) / 4; i += THREADS)
            dst[i] = __ldg(src + i);
    }

    // ---- zero the 4-byte pads (indices 48..51 of each state row) ----
    if (tid < BPB * STEPS) {
        int q = tid / STEPS;
        int r = tid - q * STEPS;
        *reinterpret_cast<unsigned int*>(&s_u[q][r * USTRIDE + AA]) = 0u;
    }

    // ---- phase 1: integer recurrence, one thread per (q, column) ----
    if (tid < BPB * AA) {
        int q = tid / AA;
        int j = tid - q * AA;
        const int* xb = x + (long)(b0 + q) * (25 * AA) + j;
        unsigned int v = 0;
        #pragma unroll
        for (int r = 0; r < 25; ++r)
            v |= ((unsigned int)__ldg(xb + r * AA)) << r;

        int st = -1, dt = 1;
        #pragma unroll
        for (int r = 0; r < STEPS; ++r) {
            int a  = (v >> r)       & 1;
            int bb = (v >> (r + 1)) & 1;
            int c  = (v >> (r + 2)) & 1;
            int de = a ^ c;
            int me = bb * (1 - (a + c)) + a * c;
            dt = dt * (1 - 2 * me);
            st = st + dt * de;
            st = st < -1 ? -1 : (st > 1 ? 1 : st);
            int ome = 1 - me;
            dt = dt * (1 - st * st * ome) - st * ome;
            int u = st + 1;                 // 0,1,2
            u = u + (u >> 1);               // remap 2 -> 3
            s_u[q][r * USTRIDE + j] = (unsigned char)u;
        }
    }
    __syncthreads();

    // ---- phase 2: thread t owns columns 4t..4t+3, one STG.128 per (q,r) ----
    const int t = tid;
    if (t >= Q4) return;   // 294 active threads

    int off_i[4], off_j[4];
    #pragma unroll
    for (int e = 0; e < 4; ++e) {
        int k = 4 * t + e;
        if (k < AA) { off_i[e] = AA; off_j[e] = k; }   // zero pad + diag key
        else {
            int p = __ldg(&g_pair[k - AA]);
            off_i[e] = p & 255;
            off_j[e] = p >> 8;
        }
    }
    // sub-LUT bases: element e -> e*2058 + t*7 (conflict-free stride 7)
    const int lb = t * LUTW;

    #pragma unroll
    for (int q = 0; q < BPB; ++q) {
        const unsigned char* uq = &s_u[q][0];
        float4* ob = reinterpret_cast<float4*>(
            out + ((long)(b0 + q) * STEPS) * ROW) + t;
        for (int r = 0; r < STEPS; ++r) {
            const unsigned char* u = uq + r * USTRIDE;
            int c0 = (int)u[off_i[0]] + (int)u[off_j[0]];
            int c1 = (int)u[off_i[1]] + (int)u[off_j[1]];
            int c2 = (int)u[off_i[2]] + (int)u[off_j[2]];
            int c3 = (int)u[off_i[3]] + (int)u[off_j[3]];
            float4 vv;
            vv.x = s_lut[0 * (Q4 * LUTW) + lb + c0];
            vv.y = s_lut[1 * (Q4 * LUTW) + lb + c1];
            vv.z = s_lut[2 * (Q4 * LUTW) + lb + c2];
            vv.w = s_lut[3 * (Q4 * LUTW) + lb + c3];
            __stcs(ob + (long)r * Q4, vv);
        }
    }
}

extern "C" void kernel_launch(void* const* d_in, const int* in_sizes, int n_in,
                              void* d_out, int out_size) {
    const int*   x  = (const int*)d_in[0];     // (4096, 25, 48) int32
    const float* ed = (const float*)d_in[1];   // (1, 48) f32
    const float* en = (const float*)d_in[2];   // (1, 1128, 4) f32
    float* out = (float*)d_out;                // (4096, 23, 1176) f32

    setup_kernel<<<(NDP + 255) / 256, 256>>>(ed, en);
    int nb = in_sizes[0] / (25 * AA);          // 4096 batches
    main_kernel<<<nb / BPB, THREADS>>>(x, out);
}

// round 8
// speedup vs baseline: 1.3551x; 1.0017x over previous
#include <cuda_runtime.h>
#include <math.h>

#define AA 48
#define NDP 1128        // nondiag pairs
#define STEPS 23
#define ROW 1176        // AA + NDP
#define BPB 2           // batches per block
#define THREADS 320
#define Q4 (ROW / 4)    // 294 column-groups (one per thread)
#define LUTW 7          // cls = u'i + u'j in 0..6, u' in {0,1,3}
#define LSZ (Q4 * LUTW) // sub-table size (2058 floats)
#define WPR 16          // words per state row: [pad][12 data words][3 pad]

// interleaved LUT: entry (k, cls) at (k&3)*LSZ + (k>>2)*LUTW + cls
__device__ float g_lut[ROW * LUTW];
__device__ int   g_pair[NDP];        // iy | (ix<<8)

__global__ void setup_kernel(const float* __restrict__ ed,
                             const float* __restrict__ en) {
    int k = blockIdx.x * blockDim.x + threadIdx.x;
    if (k < AA) {
        // diag column k: i -> zero pad, so cls = u'j in {0,1,3}
        float s = 1.f / (1.f + expf(-ed[k]));
        float* L = &g_lut[(k & 3) * LSZ + (k >> 2) * LUTW];
        #pragma unroll
        for (int c = 0; c < LUTW; ++c) L[c] = 0.f;
        L[1] = s;     // st == 0
        L[3] = 1.f;   // st == 1
    }
    if (k < NDP) {
        float f12 = 1.f / (1.f + expf(-en[k * 4 + 0]));
        float f9  = 1.f / (1.f + expf(-en[k * 4 + 1])) * f12;
        float f8  = 1.f / (1.f + expf(-en[k * 4 + 2])) * f9;
        float f6  = 1.f / (1.f + expf(-en[k * 4 + 3])) * f8;
        // u' in {0,1,3}: cls -> 0:0  1:f6  2:f9  3:f8  4:f12  6:1
        int kk = AA + k;
        float* L = &g_lut[(kk & 3) * LSZ + (kk >> 2) * LUTW];
        L[0] = 0.f; L[1] = f6;  L[2] = f9;
        L[3] = f8;  L[4] = f12; L[5] = 0.f;
        L[6] = 1.f;
        int rem = k, iy = 0;
        while (rem >= AA - 1 - iy) { rem -= AA - 1 - iy; ++iy; }
        int ix = iy + 1 + rem;
        g_pair[k] = iy | (ix << 8);
    }
}

__global__ __launch_bounds__(THREADS)
void main_kernel(const int* __restrict__ x, float* __restrict__ out) {
    __shared__ float        s_lut[ROW * LUTW];              // 32928 B
    __shared__ unsigned int s_state[BPB * STEPS * WPR];     //  2944 B

    const int tid = threadIdx.x;
    const int b0  = blockIdx.x * BPB;

    // ---- LUT copy ----
    {
        const float4* src = reinterpret_cast<const float4*>(g_lut);
        float4*       dst = reinterpret_cast<float4*>(s_lut);
        for (int i = tid; i < (ROW * LUTW) / 4; i += THREADS)
            dst[i] = __ldg(src + i);
    }

    // ---- zero pad words (front word 0, back words 13,14,15 of each row) ----
    if (tid < BPB * STEPS * 4) {
        int q  = tid / (STEPS * 4);
        int rr = tid - q * (STEPS * 4);
        int r  = rr >> 2;
        int w  = rr & 3;
        int word = (w == 0) ? 0 : (12 + w);
        s_state[(q * STEPS + r) * WPR + word] = 0u;
    }

    // ---- phase 1: integer recurrence, one thread per (q, column) ----
    if (tid < BPB * AA) {
        int q = tid / AA;
        int j = tid - q * AA;
        const int* xb = x + (long)(b0 + q) * (25 * AA) + j;
        unsigned int v = 0;
        #pragma unroll
        for (int r = 0; r < 25; ++r)
            v |= ((unsigned int)__ldg(xb + r * AA)) << r;

        unsigned char* sb = reinterpret_cast<unsigned char*>(s_state);
        int st = -1, dt = 1;
        #pragma unroll
        for (int r = 0; r < STEPS; ++r) {
            int a  = (v >> r)       & 1;
            int bb = (v >> (r + 1)) & 1;
            int c  = (v >> (r + 2)) & 1;
            int de = a ^ c;
            int me = bb * (1 - (a + c)) + a * c;
            dt = dt * (1 - 2 * me);
            st = st + dt * de;
            st = st < -1 ? -1 : (st > 1 ? 1 : st);
            int ome = 1 - me;
            dt = dt * (1 - st * st * ome) - st * ome;
            int u = st + 1;                 // 0,1,2
            u = u + (u >> 1);               // remap 2 -> 3 : u' in {0,1,3}
            sb[((q * STEPS + r) * WPR + 1) * 4 + j] = (unsigned char)u;
        }
    }
    __syncthreads();

    // ---- phase 2: thread t owns columns 4t..4t+3, one STG.128 per (q,r) ----
    const int t = tid;
    if (t >= Q4) return;   // 294 active threads

    // per-element pair indices (i -> 48 = zero pad byte for diag)
    int ii[4], jj[4];
    #pragma unroll
    for (int e = 0; e < 4; ++e) {
        int k = 4 * t + e;
        if (k < AA) { ii[e] = AA; jj[e] = k; }
        else {
            int p = __ldg(&g_pair[k - AA]);
            ii[e] = p & 255;
            jj[e] = p >> 8;
        }
    }

    // segment decomposition: elements 0..es-1 from (iyA, baseA+e),
    // elements es..3 from (iyB, baseB+e); fast iff <= 2 segments
    int es = 4;
    bool fast = true;
    #pragma unroll
    for (int e = 1; e < 4; ++e) {
        bool cont = (ii[e] == ii[e - 1]) && (jj[e] == jj[e - 1] + 1);
        if (!cont) { if (es == 4) es = e; else fast = false; }
    }
    const int iyA   = ii[0];
    const int baseA = jj[0];
    const int iyB   = (es < 4) ? ii[es] : iyA;
    const int baseB = (es < 4) ? (jj[es] - es) : baseA;
    const int wA = baseA >> 2, shA = (baseA & 3) * 8;
    const int wB = baseB >> 2, shB = (baseB & 3) * 8;   // baseB may be -1
    unsigned int selW = 0, selU = 0;
    #pragma unroll
    for (int e = 0; e < 4; ++e) {
        selW |= (unsigned int)((e < es) ? e : (4 + e)) << (4 * e);
        selU |= (unsigned int)((e < es) ? 0 : 1) << (4 * e);
    }
    // slow-path packed indices (rare: groups spanning 3 triangle rows)
    unsigned int iipk = 0, jjpk = 0;
    #pragma unroll
    for (int e = 0; e < 4; ++e) {
        iipk |= (unsigned int)ii[e] << (8 * e);
        jjpk |= (unsigned int)jj[e] << (8 * e);
    }

    const int lb = t * LUTW;

    #pragma unroll
    for (int q = 0; q < BPB; ++q) {
        float4* ob = reinterpret_cast<float4*>(
            out + ((long)(b0 + q) * STEPS) * ROW) + t;
        for (int r = 0; r < STEPS; ++r) {
            const unsigned int* uw =
                s_state + (q * STEPS + r) * WPR + 1;  // word 0 = bytes 0..3
            const unsigned char* ub =
                reinterpret_cast<const unsigned char*>(uw);
            unsigned int sums;
            if (fast) {
                unsigned int uyA = ub[iyA];
                unsigned int uyB = ub[iyB];
                unsigned int a0 = uw[wA], a1 = uw[wA + 1];
                unsigned int b0w = uw[wB], b1w = uw[wB + 1];
                unsigned int alA = __funnelshift_r(a0, a1, shA);
                unsigned int alB = __funnelshift_r(b0w, b1w, shB);
                unsigned int comb = __byte_perm(alA, alB, selW);
                unsigned int uyv  = __byte_perm(uyA | (uyB << 8), 0, selU);
                sums = comb + uyv;            // 4 byte-sums, each <= 6
            } else {
                sums = 0;
                #pragma unroll
                for (int e = 0; e < 4; ++e) {
                    unsigned int s = (unsigned int)ub[(iipk >> (8 * e)) & 255]
                                   + (unsigned int)ub[(jjpk >> (8 * e)) & 255];
                    sums |= s << (8 * e);
                }
            }
            float4 vv;
            vv.x = s_lut[0 * LSZ + lb + (sums         & 255u)];
            vv.y = s_lut[1 * LSZ + lb + ((sums >>  8) & 255u)];
            vv.z = s_lut[2 * LSZ + lb + ((sums >> 16) & 255u)];
            vv.w = s_lut[3 * LSZ + lb + ( sums >> 24        )];
            __stcs(ob + (long)r * Q4, vv);
        }
    }
}

extern "C" void kernel_launch(void* const* d_in, const int* in_sizes, int n_in,
                              void* d_out, int out_size) {
    const int*   x  = (const int*)d_in[0];     // (4096, 25, 48) int32
    const float* ed = (const float*)d_in[1];   // (1, 48) f32
    const float* en = (const float*)d_in[2];   // (1, 1128, 4) f32
    float* out = (float*)d_out;                // (4096, 23, 1176) f32

    setup_kernel<<<(NDP + 255) / 256, 256>>>(ed, en);
    int nb = in_sizes[0] / (25 * AA);          // 4096 batches
    main_kernel<<<nb / BPB, THREADS>>>(x, out);
}

// round 9
// speedup vs baseline: 1.3592x; 1.0030x over previous
#include <cuda_runtime.h>
#include <math.h>

#define AA 48
#define NDP 1128        // nondiag pairs
#define STEPS 23
#define ROW 1176        // AA + NDP
#define BPB 2           // batches per block
#define THREADS 320
#define Q4 (ROW / 4)    // 294 column-groups (one per thread)
#define LUTW 7          // cls = u'i + u'j in 0..6, u' in {0,1,3}
#define LSZ (Q4 * LUTW) // sub-table size (2058 floats)
#define WPR 16          // words per state row: [pad][12 data words][3 pad]

// interleaved LUT: entry (k, cls) at (k&3)*LSZ + (k>>2)*LUTW + cls
__device__ float g_lut[ROW * LUTW];
__device__ int   g_pair[NDP];        // iy | (ix<<8)

__global__ void setup_kernel(const float* __restrict__ ed,
                             const float* __restrict__ en) {
    int k = blockIdx.x * blockDim.x + threadIdx.x;
    if (k < AA) {
        // diag column k: i -> zero pad, so cls = u'j in {0,1,3}
        float s = 1.f / (1.f + expf(-ed[k]));
        float* L = &g_lut[(k & 3) * LSZ + (k >> 2) * LUTW];
        #pragma unroll
        for (int c = 0; c < LUTW; ++c) L[c] = 0.f;
        L[1] = s;     // st == 0
        L[3] = 1.f;   // st == 1
    }
    if (k < NDP) {
        float f12 = 1.f / (1.f + expf(-en[k * 4 + 0]));
        float f9  = 1.f / (1.f + expf(-en[k * 4 + 1])) * f12;
        float f8  = 1.f / (1.f + expf(-en[k * 4 + 2])) * f9;
        float f6  = 1.f / (1.f + expf(-en[k * 4 + 3])) * f8;
        // u' in {0,1,3}: cls -> 0:0  1:f6  2:f9  3:f8  4:f12  6:1
        int kk = AA + k;
        float* L = &g_lut[(kk & 3) * LSZ + (kk >> 2) * LUTW];
        L[0] = 0.f; L[1] = f6;  L[2] = f9;
        L[3] = f8;  L[4] = f12; L[5] = 0.f;
        L[6] = 1.f;
        int rem = k, iy = 0;
        while (rem >= AA - 1 - iy) { rem -= AA - 1 - iy; ++iy; }
        int ix = iy + 1 + rem;
        g_pair[k] = iy | (ix << 8);
    }
}

__global__ __launch_bounds__(THREADS, 6)
void main_kernel(const int* __restrict__ x, float* __restrict__ out) {
    __shared__ float        s_lut[ROW * LUTW];              // 32928 B
    __shared__ unsigned int s_state[BPB * STEPS * WPR];     //  2944 B

    const int tid = threadIdx.x;
    const int b0  = blockIdx.x * BPB;

    // ---- LUT copy ----
    {
        const float4* src = reinterpret_cast<const float4*>(g_lut);
        float4*       dst = reinterpret_cast<float4*>(s_lut);
        for (int i = tid; i < (ROW * LUTW) / 4; i += THREADS)
            dst[i] = __ldg(src + i);
    }

    // ---- zero pad words (front word 0, back words 13,14,15 of each row) ----
    if (tid < BPB * STEPS * 4) {
        int q  = tid / (STEPS * 4);
        int rr = tid - q * (STEPS * 4);
        int r  = rr >> 2;
        int w  = rr & 3;
        int word = (w == 0) ? 0 : (12 + w);
        s_state[(q * STEPS + r) * WPR + word] = 0u;
    }

    // ---- phase 1: integer recurrence, one thread per (q, column) ----
    if (tid < BPB * AA) {
        int q = tid / AA;
        int j = tid - q * AA;
        const int* xb = x + (long)(b0 + q) * (25 * AA) + j;
        unsigned int v = 0;
        #pragma unroll
        for (int r = 0; r < 25; ++r)
            v |= ((unsigned int)__ldg(xb + r * AA)) << r;

        unsigned char* sb = reinterpret_cast<unsigned char*>(s_state);
        int st = -1, dt = 1;
        #pragma unroll
        for (int r = 0; r < STEPS; ++r) {
            int a  = (v >> r)       & 1;
            int bb = (v >> (r + 1)) & 1;
            int c  = (v >> (r + 2)) & 1;
            int de = a ^ c;
            int me = bb * (1 - (a + c)) + a * c;
            dt = dt * (1 - 2 * me);
            st = st + dt * de;
            st = st < -1 ? -1 : (st > 1 ? 1 : st);
            int ome = 1 - me;
            dt = dt * (1 - st * st * ome) - st * ome;
            int u = st + 1;                 // 0,1,2
            u = u + (u >> 1);               // remap 2 -> 3 : u' in {0,1,3}
            sb[((q * STEPS + r) * WPR + 1) * 4 + j] = (unsigned char)u;
        }
    }
    __syncthreads();

    // ---- phase 2: thread t owns columns 4t..4t+3, one STG.128 per (q,r) ----
    const int t = tid;
    if (t >= Q4) return;   // 294 active threads

    // per-element pair indices (i -> 48 = zero pad byte for diag)
    int ii[4], jj[4];
    #pragma unroll
    for (int e = 0; e < 4; ++e) {
        int k = 4 * t + e;
        if (k < AA) { ii[e] = AA; jj[e] = k; }
        else {
            int p = __ldg(&g_pair[k - AA]);
            ii[e] = p & 255;
            jj[e] = p >> 8;
        }
    }

    // segment decomposition: elements 0..es-1 from (iyA, baseA+e),
    // elements es..3 from (iyB, baseB+e); fast iff <= 2 segments
    int es = 4;
    bool fast = true;
    #pragma unroll
    for (int e = 1; e < 4; ++e) {
        bool cont = (ii[e] == ii[e - 1]) && (jj[e] == jj[e - 1] + 1);
        if (!cont) { if (es == 4) es = e; else fast = false; }
    }
    const int iyA   = ii[0];
    const int baseA = jj[0];
    const int iyB   = (es < 4) ? ii[es] : iyA;
    const int baseB = (es < 4) ? (jj[es] - es) : baseA;
    const int wA = baseA >> 2, shA = (baseA & 3) * 8;
    const int wB = baseB >> 2, shB = (baseB & 3) * 8;
    unsigned int selW = 0, selU = 0;
    #pragma unroll
    for (int e = 0; e < 4; ++e) {
        selW |= (unsigned int)((e < es) ? e : (4 + e)) << (4 * e);
        selU |= (unsigned int)((e < es) ? 0 : 1) << (4 * e);
    }
    // slow-path packed indices (rare: groups spanning 3 triangle rows)
    unsigned int iipk = 0, jjpk = 0;
    #pragma unroll
    for (int e = 0; e < 4; ++e) {
        iipk |= (unsigned int)ii[e] << (8 * e);
        jjpk |= (unsigned int)jj[e] << (8 * e);
    }

    const int lb = t * LUTW;

    float4* ob0 = reinterpret_cast<float4*>(
        out + ((long)(b0 + 0) * STEPS) * ROW) + t;
    float4* ob1 = reinterpret_cast<float4*>(
        out + ((long)(b0 + 1) * STEPS) * ROW) + t;

    // r outer, q inner-unrolled: two independent LDS->add->LDS->STG chains
    for (int r = 0; r < STEPS; ++r) {
        #pragma unroll
        for (int q = 0; q < BPB; ++q) {
            const unsigned int* uw =
                s_state + (q * STEPS + r) * WPR + 1;
            const unsigned char* ub =
                reinterpret_cast<const unsigned char*>(uw);
            unsigned int sums;
            if (fast) {
                unsigned int uyA = ub[iyA];
                unsigned int uyB = ub[iyB];
                unsigned int a0 = uw[wA], a1 = uw[wA + 1];
                unsigned int b0w = uw[wB], b1w = uw[wB + 1];
                unsigned int alA = __funnelshift_r(a0, a1, shA);
                unsigned int alB = __funnelshift_r(b0w, b1w, shB);
                unsigned int comb = __byte_perm(alA, alB, selW);
                unsigned int uyv  = __byte_perm(uyA | (uyB << 8), 0, selU);
                sums = comb + uyv;            // 4 byte-sums, each <= 6
            } else {
                sums = 0;
                #pragma unroll
                for (int e = 0; e < 4; ++e) {
                    unsigned int s = (unsigned int)ub[(iipk >> (8 * e)) & 255]
                                   + (unsigned int)ub[(jjpk >> (8 * e)) & 255];
                    sums |= s << (8 * e);
                }
            }
            float4 vv;
            vv.x = s_lut[0 * LSZ + lb + (sums         & 255u)];
            vv.y = s_lut[1 * LSZ + lb + ((sums >>  8) & 255u)];
            vv.z = s_lut[2 * LSZ + lb + ((sums >> 16) & 255u)];
            vv.w = s_lut[3 * LSZ + lb + ( sums >> 24        )];
            __stcs((q == 0 ? ob0 : ob1) + (long)r * Q4, vv);
        }
    }
}

extern "C" void kernel_launch(void* const* d_in, const int* in_sizes, int n_in,
                              void* d_out, int out_size) {
    const int*   x  = (const int*)d_in[0];     // (4096, 25, 48) int32
    const float* ed = (const float*)d_in[1];   // (1, 48) f32
    const float* en = (const float*)d_in[2];   // (1, 1128, 4) f32
    float* out = (float*)d_out;                // (4096, 23, 1176) f32

    setup_kernel<<<(NDP + 255) / 256, 256>>>(ed, en);
    int nb = in_sizes[0] / (25 * AA);          // 4096 batches
    main_kernel<<<nb / BPB, THREADS>>>(x, out);
}